// round 14
// baseline (speedup 1.0000x reference)
#include <cuda_runtime.h>
#include <math.h>

#define BB 64
#define AA 8732
#define CC 81
#define GG 32
#define NEG_RATIO 3
#define IOU_THR 0.5f
#define TROWS 128
#define NBS 69          // streaming blocks per batch: ceil(8732/128)
#define NBM 35          // matching blocks per batch: ceil(8732/256)
#define HROWS 4366      // rows per k4 half (8732/2)
#define KVH 5           // ceil(4366/1024)
#define HISTSZ 6400     // 256 + 2048 + 4096

// ---------------- device scratch (no allocs allowed) ----------------
__device__ float4             g_tloc[BB * AA];
__device__ int                g_tlab[BB * AA];
__device__ unsigned long long g_bpp[BB * NBM * GG];
__device__ float              g_raw[BB * AA];
__device__ float4             g_bres[BB];
__device__ float4             g_part[BB][2];       // {cp, ls, s, cgt} per half
__device__ int                g_hist[BB][HISTSZ];  // h1 @0, h2 @256, h3 @2304
__device__ int                g_sync[BB];
__device__ int                g_npk[BB];
__device__ int                g_done;

__device__ __forceinline__ float smooth_l1(float d) {
    float ad = fabsf(d);
    return ad < 1.0f ? 0.5f * d * d : ad - 0.5f;
}

struct K1Smem {
    float gx1[GG], gy1[GG], gx2[GG], gy2[GG], garea[GG];
    float gcx[GG], gcy[GG], gw[GG], gh[GG];
    int   glab[GG];
    unsigned long long sbp[GG];
};

// ---------------- F1: fused conf-streaming (x<NBS) + matching (x>=NBS) ----------
__global__ void __launch_bounds__(256)
f1_fused(const float* __restrict__ conf,
         const float4* __restrict__ anchors,
         const float4* __restrict__ gt_boxes,
         const int*    __restrict__ gt_labels) {
    // 8 warps x 2 buffers x 324 floats = 20736 B
    __shared__ __align__(16) float sx[8 * 2 * 324];
    int b = blockIdx.y;
    int t = threadIdx.x;
    int w = t >> 5;
    int lane = t & 31;

    if (blockIdx.x >= NBS) {
        // ================= matching part (256 anchors/block) =================
        int bx = blockIdx.x - NBS;
        K1Smem* sm = reinterpret_cast<K1Smem*>(&sx[0]);

        // zero this batch's global histograms (strided across matching blocks)
        for (int i = bx * 256 + t; i < HISTSZ; i += NBM * 256)
            g_hist[b][i] = 0;

        if (t < GG) {
            float4 g = gt_boxes[b * GG + t];
            float x1 = g.x - g.z * 0.5f, y1 = g.y - g.w * 0.5f;
            float x2 = g.x + g.z * 0.5f, y2 = g.y + g.w * 0.5f;
            sm->gx1[t] = x1; sm->gy1[t] = y1; sm->gx2[t] = x2; sm->gy2[t] = y2;
            sm->garea[t] = (x2 - x1) * (y2 - y1);
            sm->gcx[t] = g.x; sm->gcy[t] = g.y; sm->gw[t] = g.z; sm->gh[t] = g.w;
            sm->glab[t] = gt_labels[b * GG + t];
            sm->sbp[t] = 0xFFFFFFFFull;
        }
        __syncthreads();

        int a = bx * 256 + t;
        bool valid = a < AA;

        float4 an = valid ? anchors[a] : make_float4(2.0f, 2.0f, 0.01f, 0.01f);
        float ax1 = an.x - an.z * 0.5f, ay1 = an.y - an.w * 0.5f;
        float ax2 = an.x + an.z * 0.5f, ay2 = an.y + an.w * 0.5f;
        float aarea = (ax2 - ax1) * (ay2 - ay1);

        int warpbase = bx * 256 + (t & ~31);
        float best = -1.0f;
        int   bidx = 0;
#pragma unroll 4
        for (int g = 0; g < GG; g++) {
            float ltx = fmaxf(sm->gx1[g], ax1), lty = fmaxf(sm->gy1[g], ay1);
            float rbx = fminf(sm->gx2[g], ax2), rby = fminf(sm->gy2[g], ay2);
            float ww = fmaxf(rbx - ltx, 0.0f), hh = fmaxf(rby - lty, 0.0f);
            float inter = ww * hh;
            bool ov = valid && (inter > 0.0f);
            float iou = ov ? __fdividef(inter, sm->garea[g] + aarea - inter) : 0.0f;
            if (valid && iou > best) { best = iou; bidx = g; }

            if (__any_sync(0xffffffffu, ov)) {
                unsigned ib = ov ? __float_as_uint(iou) : 0u;
                unsigned mx = __reduce_max_sync(0xffffffffu, ib);
                unsigned ball = __ballot_sync(0xffffffffu, ib == mx);
                if (lane == 0) {
                    unsigned win_a = (unsigned)warpbase + (unsigned)(__ffs(ball) - 1);
                    unsigned long long key =
                        (((unsigned long long)mx) << 32) |
                        (unsigned long long)(0xFFFFFFFFu - win_a);
                    atomicMax(&sm->sbp[g], key);
                }
            }
        }

        if (valid) {
            size_t idx = (size_t)b * AA + a;
            if (best > IOU_THR) {
                float4 enc;
                enc.x = (sm->gcx[bidx] - an.x) / an.z;
                enc.y = (sm->gcy[bidx] - an.y) / an.w;
                enc.z = logf(sm->gw[bidx]) - logf(an.z);
                enc.w = logf(sm->gh[bidx]) - logf(an.w);
                g_tloc[idx] = enc;
                g_tlab[idx] = sm->glab[bidx];
            } else {
                g_tlab[idx] = 0;
            }
        }

        __syncthreads();
        if (t < GG)
            g_bpp[((size_t)b * NBM + bx) * GG + t] = sm->sbp[t];
        return;
    }

    // ===== conf streaming (R11-proven): warp-autonomous reg-pipelined groups =====
    int rowstart = blockIdx.x * TROWS;
    int nrows = min(TROWS, AA - rowstart);   // 128, tail 28 (%4==0)
    size_t growb = (size_t)b * AA + rowstart;
    const float4* gsrc = reinterpret_cast<const float4*>(conf + growb * CC);

    int base = w * 16;                        // warp's first row in tile
    int ng = (base < nrows) ? min(4, (nrows - base) >> 2) : 0;
    const float4* wsrc = gsrc + w * 324;
    float* ws = sx + w * 648;                 // warp slice: 2 x 324 floats

    float4 ra, rb4, rc;
    auto ldg = [&](int g) {
        const float4* p = wsrc + g * 81;
        ra  = __ldcs(p + lane);
        rb4 = __ldcs(p + lane + 32);
        if (lane < 17) rc = __ldcs(p + lane + 64);
    };
    auto sts = [&](int g) {
        float4* d = reinterpret_cast<float4*>(ws + (g & 1) * 324);
        d[lane] = ra;
        d[lane + 32] = rb4;
        if (lane < 17) d[lane + 64] = rc;
    };

    if (ng > 0) { ldg(0); sts(0); }
    __syncwarp();

    for (int g = 0; g < ng; g++) {
        if (g + 1 < ng) ldg(g + 1);

        const float* buf = ws + (g & 1) * 324;
        float e[4];
#pragma unroll
        for (int r = 0; r < 4; r++) {
            const float* row = buf + r * CC;
            float tv = __expf(row[lane]) + __expf(row[32 + lane]);
            if (lane < 17) tv += __expf(row[64 + lane]);
            e[r] = tv;
        }
#pragma unroll
        for (int o = 16; o; o >>= 1) {
#pragma unroll
            for (int r = 0; r < 4; r++)
                e[r] += __shfl_xor_sync(0xffffffffu, e[r], o);
        }
        if (lane == 0) {
            size_t rowb = growb + base + g * 4;
            float4 res;
            res.x = __logf(e[0]) - buf[0 * CC];
            res.y = __logf(e[1]) - buf[1 * CC];
            res.z = __logf(e[2]) - buf[2 * CC];
            res.w = __logf(e[3]) - buf[3 * CC];
            *reinterpret_cast<float4*>(g_raw + rowb) = res;
        }
        __syncwarp();
        if (g + 1 < ng) { sts(g + 1); __syncwarp(); }
    }
}

// ---------------- block-parallel descending bin search (gmem hist) ----------------
__device__ __forceinline__ void find_bin_block(const int* h, int N, int P, int k,
                                               int* sres, int* swarp) {
    int t = threadIdx.x, lane = t & 31, w = t >> 5;
    int nt = N / P;
    int local = 0;
    if (t < nt)
        for (int j = 0; j < P; j++) local += h[t * P + j];
    int suf = local;
#pragma unroll
    for (int o = 1; o < 32; o <<= 1) {
        int x = __shfl_down_sync(0xffffffffu, suf, o);
        if (lane + o < 32) suf += x;
    }
    if (t < nt && lane == 0) swarp[w] = suf;
    __syncthreads();
    if (t < nt) {
        int nw = nt >> 5;
        int above = suf - local;
        for (int w2 = w + 1; w2 < nw; w2++) above += swarp[w2];
        if (above < k && k <= above + local) {
            int acc = above, bin = t * P;
            for (int j = P - 1; j >= 0; j--) {
                int c = h[t * P + j];
                if (k <= acc + c) { bin = t * P + j; break; }
                acc += c;
            }
            sres[0] = bin; sres[1] = acc;
        }
    }
    __syncthreads();
}

// ---------------- K4: 2 blocks per batch, global hist + spin barriers --------
#define NBMW 273  // ceil(AA/32) bitmap words

__device__ __forceinline__ void pair_barrier(int b, int target) {
    __syncthreads();
    if (threadIdx.x == 0) {
        __threadfence();
        atomicAdd(&g_sync[b], 1);
        volatile int* vs = &g_sync[b];
        while (*vs < target) __nanosleep(32);
    }
    __syncthreads();
    __threadfence();
}

__global__ void __launch_bounds__(1024)
k4_final(const float* __restrict__ conf,
         const float4* __restrict__ locp,
         const float4* __restrict__ anchors,
         const float4* __restrict__ gt_boxes,
         const int*    __restrict__ gt_labels,
         float* __restrict__ out) {
    __shared__ unsigned sbm[NBMW];
    __shared__ unsigned claimed_aidx[GG];
    __shared__ int      claimed_lab[GG];
    __shared__ float4   claimed_enc[GG];
    __shared__ unsigned long long skey[GG];
    __shared__ int swarp[32];
    __shared__ int sres[2];
    __shared__ float sfA[32], sfB[32], sfC[32];
    __shared__ int siA[33], siB[32];
    __shared__ int slast;
    int b = blockIdx.x >> 1;
    int hh = blockIdx.x & 1;          // half index
    int rbase = hh * HROWS;
    int t = threadIdx.x;
    int lane = t & 31, w = t >> 5;

    int* h1 = &g_hist[b][0];
    int* h2 = &g_hist[b][256];
    int* h3 = &g_hist[b][2304];

    // ---- prefetch this half's raw + labels ----
    float rawv[KVH];
    int lab[KVH];
#pragma unroll
    for (int it = 0; it < KVH; it++) {
        int i = rbase + t + it * 1024;
        if (i < rbase + HROWS) {
            rawv[it] = g_raw[(size_t)b * AA + i];
            lab[it]  = g_tlab[(size_t)b * AA + i];
        } else { rawv[it] = 0.0f; lab[it] = 0; }
    }
    for (int i = t; i < NBMW; i += 1024) sbm[i] = 0u;

    // ---- best-prior reduce (redundant in both halves; warp w = gt w) ----
    {
        unsigned long long key = 0xFFFFFFFFull;
        for (int blk = lane; blk < NBM; blk += 32) {
            unsigned long long x = g_bpp[((size_t)b * NBM + blk) * GG + w];
            if (x > key) key = x;
        }
#pragma unroll
        for (int o = 16; o; o >>= 1) {
            unsigned long long x = __shfl_xor_sync(0xffffffffu, key, o);
            if (x > key) key = x;
        }
        if (lane == 0) skey[w] = key;
    }
    __syncthreads();

    // ---- warp 0: duplicate resolution, claimed table + bitmap ----
    if (t < GG) {
        unsigned aidx = 0xFFFFFFFFu - (unsigned)(skey[t] & 0xFFFFFFFFull);
        claimed_aidx[t] = aidx;
        __syncwarp();
        bool win = true;
        for (int g2 = t + 1; g2 < GG; g2++)
            if (claimed_aidx[g2] == aidx) win = false;
        __syncwarp();
        if (win) {
            float4 gt = gt_boxes[b * GG + t];
            float4 an = anchors[aidx];
            float4 enc;
            enc.x = (gt.x - an.x) / an.z;
            enc.y = (gt.y - an.y) / an.w;
            enc.z = logf(gt.z) - logf(an.z);
            enc.w = logf(gt.w) - logf(an.w);
            claimed_enc[t] = enc;
            claimed_lab[t] = gt_labels[b * GG + t];
            atomicOr(&sbm[aidx >> 5], 1u << (aidx & 31));
        } else {
            claimed_aidx[t] = 0xFFFFFFFFu;
        }
    }
    __syncthreads();

    // ---- scan half: overrides, positives, mining bits, global hist1 ----
    unsigned v[KVH];
    float cp = 0.0f, ls = 0.0f;
    int np = 0;
#pragma unroll
    for (int it = 0; it < KVH; it++) {
        int i = rbase + t + it * 1024;
        unsigned vb = 0u;
        if (i < rbase + HROWS) {
            bool claimed = (sbm[i >> 5] >> (i & 31)) & 1u;
            int l = lab[it];
            float4 tl;
            bool have_tl = false;
            if (claimed) {
                for (int g = 0; g < GG; g++) {
                    if (claimed_aidx[g] == (unsigned)i) {
                        l = claimed_lab[g];
                        tl = claimed_enc[g];
                        have_tl = true;
                        break;
                    }
                }
            }
            if (l > 0) {
                np++;
                size_t row = (size_t)b * AA + i;
                if (!have_tl) tl = g_tloc[row];
                float c0   = conf[row * CC];
                float clab = conf[row * CC + l];
                cp += rawv[it] + c0 - clab;   // = lse - conf[lab]
                float4 lp = locp[row];
                ls += smooth_l1(lp.x - tl.x) + smooth_l1(lp.y - tl.y) +
                      smooth_l1(lp.z - tl.z) + smooth_l1(lp.w - tl.w);
            } else {
                vb = __float_as_uint(rawv[it]);
            }
        }
        v[it] = vb;
        int bin = (int)(vb >> 23);
        unsigned m = __match_any_sync(0xffffffffu, bin);
        if (bin > 0 && lane == (int)__ffs(m) - 1) atomicAdd(&h1[bin], __popc(m));
    }
    // np partial -> global
    {
        int x = np;
#pragma unroll
        for (int o = 16; o; o >>= 1) x += __shfl_xor_sync(0xffffffffu, x, o);
        if (lane == 0) siA[w] = x;
    }
    __syncthreads();
    if (t == 0) {
        int x = 0;
#pragma unroll
        for (int w2 = 0; w2 < 32; w2++) x += siA[w2];
        atomicAdd(&g_npk[b], x);
    }

    pair_barrier(b, 2);   // hist1 + np complete for both halves
    int np_total = g_npk[b];
    int k = min(NEG_RATIO * np_total, AA - 1);

    float s = 0.0f;
    int cgt = 0;
    float vk = 0.0f;
    if (k > 0) {   // same k in both halves -> consistent barrier schedule
        find_bin_block(h1, 256, 1, k, sres, swarp);
        int E = sres[0];
        int k2 = k - sres[1];

#pragma unroll
        for (int it = 0; it < KVH; it++) {
            if ((int)(v[it] >> 23) == E)
                atomicAdd(&h2[(v[it] >> 12) & 2047u], 1);
        }
        pair_barrier(b, 4);
        find_bin_block(h2, 2048, 2, k2, sres, swarp);
        unsigned P = ((unsigned)E << 11) | (unsigned)sres[0];
        int k3 = k2 - sres[1];

#pragma unroll
        for (int it = 0; it < KVH; it++) {
            if ((v[it] >> 12) == P)
                atomicAdd(&h3[v[it] & 4095u], 1);
        }
        pair_barrier(b, 6);
        find_bin_block(h3, 4096, 4, k3, sres, swarp);
        unsigned lo = (P << 12) | (unsigned)sres[0];  // exact k-th largest bits
        vk = __uint_as_float(lo);

#pragma unroll
        for (int it = 0; it < KVH; it++) {
            if (v[it] > lo) { s += __uint_as_float(v[it]); cgt++; }
        }
    }

    // ---- per-half reduce of (cp, ls, s, cgt) ----
#pragma unroll
    for (int o = 16; o; o >>= 1) {
        cp  += __shfl_xor_sync(0xffffffffu, cp, o);
        ls  += __shfl_xor_sync(0xffffffffu, ls, o);
        s   += __shfl_xor_sync(0xffffffffu, s, o);
        cgt += __shfl_xor_sync(0xffffffffu, cgt, o);
    }
    if (lane == 0) { sfA[w] = cp; sfB[w] = ls; sfC[w] = s; siB[w] = cgt; }
    __syncthreads();
    if (t == 0) {
        float cpt = 0.f, lst = 0.f, st = 0.f;
        int cgtt = 0;
#pragma unroll
        for (int w2 = 0; w2 < 32; w2++) {
            cpt += sfA[w2]; lst += sfB[w2]; st += sfC[w2]; cgtt += siB[w2];
        }
        g_part[b][hh] = make_float4(cpt, lst, st, (float)cgtt);
    }

    pair_barrier(b, (k > 0) ? 8 : 4);   // partials visible

    if (hh == 1) return;   // half 1 done; half 0 finalizes

    if (t == 0) {
        float4 p0 = g_part[b][0];
        float4 p1 = g_part[b][1];
        float st = p0.z + p1.z;
        int cgtt = (int)p0.w + (int)p1.w;
        float result = (k > 0) ? (st + (float)(k - cgtt) * vk) : 0.0f;
        g_bres[b] = make_float4(p0.y + p1.y,        // locsum
                                p0.x + p1.x,        // clspos
                                result,             // clsneg
                                (float)np_total);
        __threadfence();
        int done = atomicAdd(&g_done, 1);
        slast = (done == BB - 1) ? 1 : 0;
    }
    __syncthreads();

    // ---- last finalizer: cross-batch combine + counter resets ----
    if (slast) {
        if (t < 64) {
            float4 r = g_bres[t];
            float loc = r.x, cpos = r.y, cn = r.z;
            int npb = (int)r.w;
            int nsb = npb + min(NEG_RATIO * npb, AA - 1);
#pragma unroll
            for (int o = 16; o; o >>= 1) {
                loc  += __shfl_xor_sync(0xffffffffu, loc, o);
                cpos += __shfl_xor_sync(0xffffffffu, cpos, o);
                cn   += __shfl_xor_sync(0xffffffffu, cn, o);
                npb  += __shfl_xor_sync(0xffffffffu, npb, o);
                nsb  += __shfl_xor_sync(0xffffffffu, nsb, o);
            }
            if (lane == 0) {
                sfA[w] = loc; sfB[w] = cpos; sfC[w] = cn;
                siA[w] = npb; siB[w] = nsb;
            }
        }
        // reset counters for next graph replay
        if (t < BB) { g_sync[t] = 0; g_npk[t] = 0; }
        __syncthreads();
        if (t == 0) {
            float loct = sfA[0] + sfA[1];
            float cpt  = sfB[0] + sfB[1];
            float cnt  = sfC[0] + sfC[1];
            long long npt = siA[0] + siA[1];
            long long nst = siB[0] + siB[1];
            float cls = cpt + cnt +
                        (float)((long long)BB * AA - nst) * logf((float)CC);
            out[0] = (loct + cls) / (float)npt;
            g_done = 0;
        }
    }
}

// ---------------- launch ----------------
extern "C" void kernel_launch(void* const* d_in, const int* in_sizes, int n_in,
                              void* d_out, int out_size) {
    const float4* loc_pred  = (const float4*)d_in[0];
    const float*  conf_pred = (const float*)d_in[1];
    const float4* anchors   = (const float4*)d_in[2];
    const float4* gt_boxes  = (const float4*)d_in[3];
    const int*    gt_labels = (const int*)d_in[4];
    float* out = (float*)d_out;

    dim3 gf(NBS + NBM, BB);   // 104 x 64 blocks of 256 threads
    f1_fused<<<gf, 256>>>(conf_pred, anchors, gt_boxes, gt_labels);

    k4_final<<<2 * BB, 1024>>>(conf_pred, loc_pred, anchors, gt_boxes, gt_labels, out);
}

// round 15
// speedup vs baseline: 1.0635x; 1.0635x over previous
#include <cuda_runtime.h>
#include <math.h>

#define BB 64
#define AA 8732
#define CC 81
#define GG 32
#define NEG_RATIO 3
#define IOU_THR 0.5f
#define TROWS 128
#define SROWS 32
#define NBS 69          // streaming blocks per batch: ceil(8732/128)
#define NBM 35          // matching blocks per batch: ceil(8732/256)

// ---------------- device scratch (no allocs allowed) ----------------
__device__ float4             g_tloc[BB * AA];
__device__ int                g_tlab[BB * AA];
__device__ unsigned long long g_bpp[BB * NBM * GG];
__device__ float              g_raw[BB * AA];       // lse - conf0 per row
__device__ float4             g_bres[BB];
__device__ int                g_done;

__device__ __forceinline__ float smooth_l1(float d) {
    float ad = fabsf(d);
    return ad < 1.0f ? 0.5f * d * d : ad - 0.5f;
}

__device__ __forceinline__ unsigned smem_u32(const void* p) {
    return (unsigned)__cvta_generic_to_shared(p);
}
__device__ __forceinline__ void mbar_init(unsigned addr, unsigned cnt) {
    asm volatile("mbarrier.init.shared.b64 [%0], %1;" :: "r"(addr), "r"(cnt) : "memory");
}
__device__ __forceinline__ void mbar_expect_tx(unsigned addr, unsigned bytes) {
    asm volatile("mbarrier.arrive.expect_tx.shared.b64 _, [%0], %1;"
                 :: "r"(addr), "r"(bytes) : "memory");
}
__device__ __forceinline__ void bulk_copy(unsigned dst, const void* src,
                                          unsigned bytes, unsigned mbar) {
    asm volatile(
        "cp.async.bulk.shared::cluster.global.mbarrier::complete_tx::bytes "
        "[%0], [%1], %2, [%3];"
        :: "r"(dst), "l"(src), "r"(bytes), "r"(mbar) : "memory");
}
__device__ __forceinline__ void mbar_wait(unsigned addr, unsigned parity) {
    unsigned done;
    do {
        asm volatile(
            "{\n\t.reg .pred p;\n\t"
            "mbarrier.try_wait.parity.shared.b64 p, [%1], %2;\n\t"
            "selp.b32 %0, 1, 0, p;\n\t}"
            : "=r"(done) : "r"(addr), "r"(parity) : "memory");
    } while (!done);
}

struct K1Smem {
    float gx1[GG], gy1[GG], gx2[GG], gy2[GG], garea[GG];
    float gcx[GG], gcy[GG], gw[GG], gh[GG];
    int   glab[GG];
    unsigned long long sbp[GG];
};

struct StSmem {
    float buf[4][SROWS * CC];        // 4 x 10368 B = 41472 B
    unsigned long long mbar[4];
};

union FSmem {
    StSmem st;
    K1Smem match;
};

// ---------------- F1: fused conf-streaming (x<NBS) + matching (x>=NBS) ----------
__global__ void __launch_bounds__(256)
f1_fused(const float* __restrict__ conf,
         const float4* __restrict__ anchors,
         const float4* __restrict__ gt_boxes,
         const int*    __restrict__ gt_labels) {
    __shared__ __align__(128) FSmem sp;
    int b = blockIdx.y;
    int t = threadIdx.x;
    int w = t >> 5;
    int lane = t & 31;

    if (blockIdx.x >= NBS) {
        // ================= matching part (256 anchors/block) =================
        int bx = blockIdx.x - NBS;
        K1Smem* sm = &sp.match;

        if (bx == 0 && b == 0 && t == 0) g_done = 0;

        if (t < GG) {
            float4 g = gt_boxes[b * GG + t];
            float x1 = g.x - g.z * 0.5f, y1 = g.y - g.w * 0.5f;
            float x2 = g.x + g.z * 0.5f, y2 = g.y + g.w * 0.5f;
            sm->gx1[t] = x1; sm->gy1[t] = y1; sm->gx2[t] = x2; sm->gy2[t] = y2;
            sm->garea[t] = (x2 - x1) * (y2 - y1);
            sm->gcx[t] = g.x; sm->gcy[t] = g.y; sm->gw[t] = g.z; sm->gh[t] = g.w;
            sm->glab[t] = gt_labels[b * GG + t];
            sm->sbp[t] = 0xFFFFFFFFull;
        }
        __syncthreads();

        int a = bx * 256 + t;
        bool valid = a < AA;

        float4 an = valid ? anchors[a] : make_float4(2.0f, 2.0f, 0.01f, 0.01f);
        float ax1 = an.x - an.z * 0.5f, ay1 = an.y - an.w * 0.5f;
        float ax2 = an.x + an.z * 0.5f, ay2 = an.y + an.w * 0.5f;
        float aarea = (ax2 - ax1) * (ay2 - ay1);

        int warpbase = bx * 256 + (t & ~31);
        float best = -1.0f;
        int   bidx = 0;
#pragma unroll 4
        for (int g = 0; g < GG; g++) {
            float ltx = fmaxf(sm->gx1[g], ax1), lty = fmaxf(sm->gy1[g], ay1);
            float rbx = fminf(sm->gx2[g], ax2), rby = fminf(sm->gy2[g], ay2);
            float ww = fmaxf(rbx - ltx, 0.0f), hh = fmaxf(rby - lty, 0.0f);
            float inter = ww * hh;
            bool ov = valid && (inter > 0.0f);
            float iou = ov ? __fdividef(inter, sm->garea[g] + aarea - inter) : 0.0f;
            if (valid && iou > best) { best = iou; bidx = g; }

            if (__any_sync(0xffffffffu, ov)) {
                unsigned ib = ov ? __float_as_uint(iou) : 0u;
                unsigned mx = __reduce_max_sync(0xffffffffu, ib);
                unsigned ball = __ballot_sync(0xffffffffu, ib == mx);
                if (lane == 0) {
                    unsigned win_a = (unsigned)warpbase + (unsigned)(__ffs(ball) - 1);
                    unsigned long long key =
                        (((unsigned long long)mx) << 32) |
                        (unsigned long long)(0xFFFFFFFFu - win_a);
                    atomicMax(&sm->sbp[g], key);
                }
            }
        }

        if (valid) {
            size_t idx = (size_t)b * AA + a;
            if (best > IOU_THR) {
                float4 enc;
                enc.x = (sm->gcx[bidx] - an.x) / an.z;
                enc.y = (sm->gcy[bidx] - an.y) / an.w;
                enc.z = logf(sm->gw[bidx]) - logf(an.z);
                enc.w = logf(sm->gh[bidx]) - logf(an.w);
                g_tloc[idx] = enc;
                g_tlab[idx] = sm->glab[bidx];
            } else {
                g_tlab[idx] = 0;
            }
        }

        __syncthreads();
        if (t < GG)
            g_bpp[((size_t)b * NBM + bx) * GG + t] = sm->sbp[t];
        return;
    }

    // ===== conf streaming: bulk-async (UBLKCP) 4-buffer pipeline =====
    int rowstart = blockIdx.x * TROWS;
    int nrows = min(TROWS, AA - rowstart);      // 128, tail 28
    int nsub = (nrows + SROWS - 1) / SROWS;     // 4 (tail: 1)
    size_t growb = (size_t)b * AA + rowstart;
    const float* gsrc = conf + growb * CC;      // 16B-aligned (multiple of 41472/16)

    unsigned mb0 = smem_u32(&sp.st.mbar[0]);
    if (t < nsub) mbar_init(mb0 + t * 8, 1);
    __syncthreads();
    if (t == 0) {
        // issue ALL sub-tile copies up front: 41.5 KB in flight immediately
        for (int s = 0; s < nsub; s++) {
            unsigned bytes = (unsigned)(min(SROWS, nrows - s * SROWS) * CC * 4);
            unsigned mb = mb0 + s * 8;
            mbar_expect_tx(mb, bytes);
            bulk_copy(smem_u32(&sp.st.buf[s][0]), gsrc + (size_t)s * SROWS * CC,
                      bytes, mb);
        }
    }
    __syncthreads();   // mbar issuance visible to all warps

    // each warp owns rows [4w, 4w+4) of every sub-tile
    for (int s = 0; s < nsub; s++) {
        int srows = min(SROWS, nrows - s * SROWS);   // 32 or 28 (%4==0)
        int r0 = w * 4;
        if (r0 >= srows) continue;
        mbar_wait(mb0 + s * 8, 0);

        const float* buf = &sp.st.buf[s][r0 * CC];
        float e[4];
#pragma unroll
        for (int r = 0; r < 4; r++) {
            const float* row = buf + r * CC;
            float tv = __expf(row[lane]) + __expf(row[32 + lane]);
            if (lane < 17) tv += __expf(row[64 + lane]);
            e[r] = tv;
        }
#pragma unroll
        for (int o = 16; o; o >>= 1) {
#pragma unroll
            for (int r = 0; r < 4; r++)
                e[r] += __shfl_xor_sync(0xffffffffu, e[r], o);
        }
        if (lane == 0) {
            size_t rowb = growb + s * SROWS + r0;
            float4 res;
            res.x = __logf(e[0]) - buf[0 * CC];
            res.y = __logf(e[1]) - buf[1 * CC];
            res.z = __logf(e[2]) - buf[2 * CC];
            res.w = __logf(e[3]) - buf[3 * CC];
            *reinterpret_cast<float4*>(g_raw + rowb) = res;  // raw = lse - conf0
        }
    }
}

// ---------------- block-parallel descending bin search ----------------
__device__ __forceinline__ void find_bin_block(const int* h, int N, int P, int k,
                                               int* sres, int* swarp) {
    int t = threadIdx.x, lane = t & 31, w = t >> 5;
    int nt = N / P;
    int local = 0;
    if (t < nt)
        for (int j = 0; j < P; j++) local += h[t * P + j];
    int suf = local;
#pragma unroll
    for (int o = 1; o < 32; o <<= 1) {
        int x = __shfl_down_sync(0xffffffffu, suf, o);
        if (lane + o < 32) suf += x;
    }
    if (t < nt && lane == 0) swarp[w] = suf;
    __syncthreads();
    if (t < nt) {
        int nw = nt >> 5;
        int above = suf - local;
        for (int w2 = w + 1; w2 < nw; w2++) above += swarp[w2];
        if (above < k && k <= above + local) {
            int acc = above, bin = t * P;
            for (int j = P - 1; j >= 0; j--) {
                int c = h[t * P + j];
                if (k <= acc + c) { bin = t * P + j; break; }
                acc += c;
            }
            sres[0] = bin; sres[1] = acc;
        }
    }
    __syncthreads();
}

// ---------------- K4': in-smem scatter + positives + radix top-k + final --------
#define KV 9      // ceil(AA/1024)
#define NBMW 273  // ceil(AA/32) bitmap words

__global__ void __launch_bounds__(1024)
k4_final(const float* __restrict__ conf,
         const float4* __restrict__ locp,
         const float4* __restrict__ anchors,
         const float4* __restrict__ gt_boxes,
         const int*    __restrict__ gt_labels,
         float* __restrict__ out) {
    __shared__ int h1[256];
    __shared__ int h2[2048];
    __shared__ int h3[4096];
    __shared__ unsigned sbm[NBMW];
    __shared__ unsigned claimed_aidx[GG];
    __shared__ int      claimed_lab[GG];
    __shared__ float4   claimed_enc[GG];
    __shared__ unsigned long long skey[GG];
    __shared__ int swarp[32];
    __shared__ int sres[2];
    __shared__ float sfA[32], sfB[32], sfC[32];
    __shared__ int siA[33], siB[32];
    __shared__ int slast;
    int b = blockIdx.x;
    int t = threadIdx.x;
    int lane = t & 31, w = t >> 5;

    // ---- prefetch raw + pre-scatter labels ----
    float rawv[KV];
    int lab[KV];
#pragma unroll
    for (int it = 0; it < KV; it++) {
        int i = t + it * 1024;
        if (i < AA) {
            rawv[it] = g_raw[(size_t)b * AA + i];
            lab[it]  = g_tlab[(size_t)b * AA + i];
        } else { rawv[it] = 0.0f; lab[it] = 0; }
    }
    for (int i = t; i < 256;  i += 1024) h1[i] = 0;
    for (int i = t; i < 2048; i += 1024) h2[i] = 0;
    for (int i = t; i < 4096; i += 1024) h3[i] = 0;
    for (int i = t; i < NBMW; i += 1024) sbm[i] = 0u;

    // ---- parallel best-prior partial reduce (warp w = gt w) ----
    {
        unsigned long long key = 0xFFFFFFFFull;
        for (int blk = lane; blk < NBM; blk += 32) {
            unsigned long long x = g_bpp[((size_t)b * NBM + blk) * GG + w];
            if (x > key) key = x;
        }
#pragma unroll
        for (int o = 16; o; o >>= 1) {
            unsigned long long x = __shfl_xor_sync(0xffffffffu, key, o);
            if (x > key) key = x;
        }
        if (lane == 0) skey[w] = key;
    }
    __syncthreads();

    // ---- warp 0: duplicate resolution, claimed table + bitmap (smem only) ----
    if (t < GG) {
        unsigned aidx = 0xFFFFFFFFu - (unsigned)(skey[t] & 0xFFFFFFFFull);
        claimed_aidx[t] = aidx;
        __syncwarp();
        bool win = true;
        for (int g2 = t + 1; g2 < GG; g2++)
            if (claimed_aidx[g2] == aidx) win = false;  // later gt wins duplicates
        __syncwarp();
        if (win) {
            float4 gt = gt_boxes[b * GG + t];
            float4 an = anchors[aidx];
            float4 enc;
            enc.x = (gt.x - an.x) / an.z;
            enc.y = (gt.y - an.y) / an.w;
            enc.z = logf(gt.z) - logf(an.z);
            enc.w = logf(gt.w) - logf(an.w);
            claimed_enc[t] = enc;
            claimed_lab[t] = gt_labels[b * GG + t];
            atomicOr(&sbm[aidx >> 5], 1u << (aidx & 31));
        } else {
            claimed_aidx[t] = 0xFFFFFFFFu;
        }
    }
    __syncthreads();

    // ---- per-row: apply overrides, count positives, build mining values ----
    unsigned v[KV];
    float cp = 0.0f, ls = 0.0f;
    int np = 0;
#pragma unroll
    for (int it = 0; it < KV; it++) {
        int i = t + it * 1024;
        if (i < AA) {
            bool claimed = (sbm[i >> 5] >> (i & 31)) & 1u;
            int l = lab[it];
            float4 tl;
            bool have_tl = false;
            if (claimed) {
                for (int g = 0; g < GG; g++) {
                    if (claimed_aidx[g] == (unsigned)i) {
                        l = claimed_lab[g];
                        tl = claimed_enc[g];
                        have_tl = true;
                        break;
                    }
                }
            }
            bool pos = l > 0;
            if (pos) {
                np++;
                size_t row = (size_t)b * AA + i;
                if (!have_tl) tl = g_tloc[row];
                float c0   = conf[row * CC];
                float clab = conf[row * CC + l];
                cp += rawv[it] + c0 - clab;   // = lse - conf[lab]
                float4 lp = locp[row];
                ls += smooth_l1(lp.x - tl.x) + smooth_l1(lp.y - tl.y) +
                      smooth_l1(lp.z - tl.z) + smooth_l1(lp.w - tl.w);
                v[it] = 0u;
            } else {
                v[it] = __float_as_uint(rawv[it]);
            }
        } else v[it] = 0u;
    }
    {
        int x = np;
#pragma unroll
        for (int o = 16; o; o >>= 1) x += __shfl_xor_sync(0xffffffffu, x, o);
        if (lane == 0) siA[w] = x;
    }
    __syncthreads();
    if (t < 32) {
        int x = siA[t];
#pragma unroll
        for (int o = 16; o; o >>= 1) x += __shfl_xor_sync(0xffffffffu, x, o);
        if (t == 0) siA[32] = x;
    }
    __syncthreads();
    int np_total = siA[32];
    int k = min(NEG_RATIO * np_total, AA - 1);

    // ---- 3-round radix select ----
    float s = 0.0f;
    int cgt = 0;
    float vk = 0.0f;
    if (k > 0) {
#pragma unroll
        for (int it = 0; it < KV; it++) {
            int bin = (int)(v[it] >> 23);
            unsigned m = __match_any_sync(0xffffffffu, bin);
            if (lane == __ffs(m) - 1) atomicAdd(&h1[bin], __popc(m));
        }
        __syncthreads();
        find_bin_block(h1, 256, 1, k, sres, swarp);
        int E = sres[0];
        int k2 = k - sres[1];

#pragma unroll
        for (int it = 0; it < KV; it++) {
            if ((int)(v[it] >> 23) == E)
                atomicAdd(&h2[(v[it] >> 12) & 2047u], 1);
        }
        __syncthreads();
        find_bin_block(h2, 2048, 2, k2, sres, swarp);
        unsigned P = ((unsigned)E << 11) | (unsigned)sres[0];
        int k3 = k2 - sres[1];

#pragma unroll
        for (int it = 0; it < KV; it++) {
            if ((v[it] >> 12) == P)
                atomicAdd(&h3[v[it] & 4095u], 1);
        }
        __syncthreads();
        find_bin_block(h3, 4096, 4, k3, sres, swarp);
        unsigned lo = (P << 12) | (unsigned)sres[0];  // exact k-th largest bits
        vk = __uint_as_float(lo);

#pragma unroll
        for (int it = 0; it < KV; it++) {
            if (v[it] > lo) { s += __uint_as_float(v[it]); cgt++; }
        }
    }

    // ---- combined block reduce ----
#pragma unroll
    for (int o = 16; o; o >>= 1) {
        cp  += __shfl_xor_sync(0xffffffffu, cp, o);
        ls  += __shfl_xor_sync(0xffffffffu, ls, o);
        s   += __shfl_xor_sync(0xffffffffu, s, o);
        cgt += __shfl_xor_sync(0xffffffffu, cgt, o);
    }
    if (lane == 0) { sfA[w] = cp; sfB[w] = ls; sfC[w] = s; siB[w] = cgt; }
    __syncthreads();
    if (t == 0) {
        float cpt = 0.f, lst = 0.f, st = 0.f;
        int cgtt = 0;
#pragma unroll
        for (int w2 = 0; w2 < 32; w2++) {
            cpt += sfA[w2]; lst += sfB[w2]; st += sfC[w2]; cgtt += siB[w2];
        }
        float result = (k > 0) ? (st + (float)(k - cgtt) * vk) : 0.0f;
        g_bres[b] = make_float4(lst, cpt, result, (float)np_total);
        __threadfence();
        int done = atomicAdd(&g_done, 1);
        slast = (done == BB - 1) ? 1 : 0;
    }
    __syncthreads();

    // ---- last block: parallel final combine ----
    if (slast && w < 2) {  // threads 0..63, one per batch
        float4 r = g_bres[t];
        float loc = r.x, cpos = r.y, cn = r.z;
        int npb = (int)r.w;
        int nsb = npb + min(NEG_RATIO * npb, AA - 1);
#pragma unroll
        for (int o = 16; o; o >>= 1) {
            loc  += __shfl_xor_sync(0xffffffffu, loc, o);
            cpos += __shfl_xor_sync(0xffffffffu, cpos, o);
            cn   += __shfl_xor_sync(0xffffffffu, cn, o);
            npb  += __shfl_xor_sync(0xffffffffu, npb, o);
            nsb  += __shfl_xor_sync(0xffffffffu, nsb, o);
        }
        if (lane == 0) {
            sfA[w] = loc; sfB[w] = cpos; sfC[w] = cn;
            siA[w] = npb; siB[w] = nsb;
        }
        __syncwarp();
        if (t == 0) {
            float loct = sfA[0] + sfA[1];
            float cpt  = sfB[0] + sfB[1];
            float cnt  = sfC[0] + sfC[1];
            long long npt = siA[0] + siA[1];
            long long nst = siB[0] + siB[1];
            float cls = cpt + cnt +
                        (float)((long long)BB * AA - nst) * logf((float)CC);
            out[0] = (loct + cls) / (float)npt;
        }
    }
}

// ---------------- launch ----------------
extern "C" void kernel_launch(void* const* d_in, const int* in_sizes, int n_in,
                              void* d_out, int out_size) {
    const float4* loc_pred  = (const float4*)d_in[0];
    const float*  conf_pred = (const float*)d_in[1];
    const float4* anchors   = (const float4*)d_in[2];
    const float4* gt_boxes  = (const float4*)d_in[3];
    const int*    gt_labels = (const int*)d_in[4];
    float* out = (float*)d_out;

    dim3 gf(NBS + NBM, BB);   // 104 x 64 blocks of 256 threads
    f1_fused<<<gf, 256>>>(conf_pred, anchors, gt_boxes, gt_labels);

    k4_final<<<BB, 1024>>>(conf_pred, loc_pred, anchors, gt_boxes, gt_labels, out);
}

// round 16
// speedup vs baseline: 1.0937x; 1.0283x over previous
#include <cuda_runtime.h>
#include <math.h>

#define BB 64
#define AA 8732
#define CC 81
#define GG 32
#define NEG_RATIO 3
#define IOU_THR 0.5f
#define TROWS 64        // rows per streaming block (4 threads per row)
#define NBS 137         // streaming blocks per batch: ceil(8732/64)
#define NBM 35          // matching blocks per batch: ceil(8732/256)

// ---------------- device scratch (no allocs allowed) ----------------
__device__ float4             g_tloc[BB * AA];
__device__ int                g_tlab[BB * AA];
__device__ unsigned long long g_bpp[BB * NBM * GG];
__device__ float              g_raw[BB * AA];       // lse - conf0 per row
__device__ float4             g_bres[BB];
__device__ int                g_done;

__device__ __forceinline__ float smooth_l1(float d) {
    float ad = fabsf(d);
    return ad < 1.0f ? 0.5f * d * d : ad - 0.5f;
}

struct K1Smem {
    float gx1[GG], gy1[GG], gx2[GG], gy2[GG], garea[GG];
    float gcx[GG], gcy[GG], gw[GG], gh[GG];
    int   glab[GG];
    unsigned long long sbp[GG];
};

union FSmem {
    float   stream[TROWS * CC];   // 20736 B
    K1Smem  match;
};

// ---------------- F1: fused conf-streaming (x<NBS) + matching (x>=NBS) ----------
__global__ void __launch_bounds__(256)
f1_fused(const float* __restrict__ conf,
         const float4* __restrict__ anchors,
         const float4* __restrict__ gt_boxes,
         const int*    __restrict__ gt_labels) {
    __shared__ __align__(16) FSmem sp;
    int b = blockIdx.y;
    int t = threadIdx.x;
    int lane = t & 31;

    if (blockIdx.x >= NBS) {
        // ================= matching part (256 anchors/block) =================
        int bx = blockIdx.x - NBS;
        K1Smem* sm = &sp.match;

        if (bx == 0 && b == 0 && t == 0) g_done = 0;

        if (t < GG) {
            float4 g = gt_boxes[b * GG + t];
            float x1 = g.x - g.z * 0.5f, y1 = g.y - g.w * 0.5f;
            float x2 = g.x + g.z * 0.5f, y2 = g.y + g.w * 0.5f;
            sm->gx1[t] = x1; sm->gy1[t] = y1; sm->gx2[t] = x2; sm->gy2[t] = y2;
            sm->garea[t] = (x2 - x1) * (y2 - y1);
            sm->gcx[t] = g.x; sm->gcy[t] = g.y; sm->gw[t] = g.z; sm->gh[t] = g.w;
            sm->glab[t] = gt_labels[b * GG + t];
            sm->sbp[t] = 0xFFFFFFFFull;
        }
        __syncthreads();

        int a = bx * 256 + t;
        bool valid = a < AA;

        float4 an = valid ? anchors[a] : make_float4(2.0f, 2.0f, 0.01f, 0.01f);
        float ax1 = an.x - an.z * 0.5f, ay1 = an.y - an.w * 0.5f;
        float ax2 = an.x + an.z * 0.5f, ay2 = an.y + an.w * 0.5f;
        float aarea = (ax2 - ax1) * (ay2 - ay1);

        int warpbase = bx * 256 + (t & ~31);
        float best = -1.0f;
        int   bidx = 0;
#pragma unroll 4
        for (int g = 0; g < GG; g++) {
            float ltx = fmaxf(sm->gx1[g], ax1), lty = fmaxf(sm->gy1[g], ay1);
            float rbx = fminf(sm->gx2[g], ax2), rby = fminf(sm->gy2[g], ay2);
            float ww = fmaxf(rbx - ltx, 0.0f), hh = fmaxf(rby - lty, 0.0f);
            float inter = ww * hh;
            bool ov = valid && (inter > 0.0f);
            float iou = ov ? __fdividef(inter, sm->garea[g] + aarea - inter) : 0.0f;
            if (valid && iou > best) { best = iou; bidx = g; }

            if (__any_sync(0xffffffffu, ov)) {
                unsigned ib = ov ? __float_as_uint(iou) : 0u;
                unsigned mx = __reduce_max_sync(0xffffffffu, ib);
                unsigned ball = __ballot_sync(0xffffffffu, ib == mx);
                if (lane == 0) {
                    unsigned win_a = (unsigned)warpbase + (unsigned)(__ffs(ball) - 1);
                    unsigned long long key =
                        (((unsigned long long)mx) << 32) |
                        (unsigned long long)(0xFFFFFFFFu - win_a);
                    atomicMax(&sm->sbp[g], key);
                }
            }
        }

        if (valid) {
            size_t idx = (size_t)b * AA + a;
            if (best > IOU_THR) {
                float4 enc;
                enc.x = (sm->gcx[bidx] - an.x) / an.z;
                enc.y = (sm->gcy[bidx] - an.y) / an.w;
                enc.z = logf(sm->gw[bidx]) - logf(an.z);
                enc.w = logf(sm->gh[bidx]) - logf(an.w);
                g_tloc[idx] = enc;
                g_tlab[idx] = sm->glab[bidx];
            } else {
                g_tlab[idx] = 0;
            }
        }

        __syncthreads();
        if (t < GG)
            g_bpp[((size_t)b * NBM + bx) * GG + t] = sm->sbp[t];
        return;
    }

    // ===== conf streaming: coalesced stage + 4-threads-per-row reduce =====
    int rowstart = blockIdx.x * TROWS;
    int nrows = min(TROWS, AA - rowstart);        // 64, tail 28
    size_t growb = (size_t)b * AA + rowstart;

    const float4* src = reinterpret_cast<const float4*>(conf + growb * CC);
    float4* dst = reinterpret_cast<float4*>(sp.stream);
    int nv = nrows * CC / 4;                       // 1296 (tail 567)
#pragma unroll 6
    for (int i = t; i < nv; i += 256)
        dst[i] = __ldcs(src + i);
    __syncthreads();

    int r = t >> 2;                                // row 0..63
    int q = t & 3;                                 // quarter
    int rr = min(r, nrows - 1);                    // clamp: all lanes run shuffles
    const float* row = sp.stream + rr * CC;
    float e = 0.0f;
    // c = q, q+4, ...  -> smem word (81*rr + c): bank 17*rr + q + 4j, conflict-free
#pragma unroll
    for (int c = q; c < CC; c += 4)
        e += __expf(row[c]);
    e += __shfl_xor_sync(0xffffffffu, e, 1);
    e += __shfl_xor_sync(0xffffffffu, e, 2);
    if (q == 0 && r < nrows)
        g_raw[growb + r] = __logf(e) - row[0];     // raw = lse - conf0
}

// ---------------- block-parallel descending bin search ----------------
__device__ __forceinline__ void find_bin_block(const int* h, int N, int P, int k,
                                               int* sres, int* swarp) {
    int t = threadIdx.x, lane = t & 31, w = t >> 5;
    int nt = N / P;
    int local = 0;
    if (t < nt)
        for (int j = 0; j < P; j++) local += h[t * P + j];
    int suf = local;
#pragma unroll
    for (int o = 1; o < 32; o <<= 1) {
        int x = __shfl_down_sync(0xffffffffu, suf, o);
        if (lane + o < 32) suf += x;
    }
    if (t < nt && lane == 0) swarp[w] = suf;
    __syncthreads();
    if (t < nt) {
        int nw = nt >> 5;
        int above = suf - local;
        for (int w2 = w + 1; w2 < nw; w2++) above += swarp[w2];
        if (above < k && k <= above + local) {
            int acc = above, bin = t * P;
            for (int j = P - 1; j >= 0; j--) {
                int c = h[t * P + j];
                if (k <= acc + c) { bin = t * P + j; break; }
                acc += c;
            }
            sres[0] = bin; sres[1] = acc;
        }
    }
    __syncthreads();
}

// ---------------- K4': in-smem scatter + positives + radix top-k + final --------
#define KV 9      // ceil(AA/1024)
#define NBMW 273  // ceil(AA/32) bitmap words

__global__ void __launch_bounds__(1024)
k4_final(const float* __restrict__ conf,
         const float4* __restrict__ locp,
         const float4* __restrict__ anchors,
         const float4* __restrict__ gt_boxes,
         const int*    __restrict__ gt_labels,
         float* __restrict__ out) {
    __shared__ int h1[256];
    __shared__ int h2[2048];
    __shared__ int h3[4096];
    __shared__ unsigned sbm[NBMW];
    __shared__ unsigned claimed_aidx[GG];
    __shared__ int      claimed_lab[GG];
    __shared__ float4   claimed_enc[GG];
    __shared__ unsigned long long skey[GG];
    __shared__ int swarp[32];
    __shared__ int sres[2];
    __shared__ float sfA[32], sfB[32], sfC[32];
    __shared__ int siA[33], siB[32];
    __shared__ int slast;
    int b = blockIdx.x;
    int t = threadIdx.x;
    int lane = t & 31, w = t >> 5;

    // ---- prefetch raw + pre-scatter labels ----
    float rawv[KV];
    int lab[KV];
#pragma unroll
    for (int it = 0; it < KV; it++) {
        int i = t + it * 1024;
        if (i < AA) {
            rawv[it] = g_raw[(size_t)b * AA + i];
            lab[it]  = g_tlab[(size_t)b * AA + i];
        } else { rawv[it] = 0.0f; lab[it] = 0; }
    }
    for (int i = t; i < 256;  i += 1024) h1[i] = 0;
    for (int i = t; i < 2048; i += 1024) h2[i] = 0;
    for (int i = t; i < 4096; i += 1024) h3[i] = 0;
    for (int i = t; i < NBMW; i += 1024) sbm[i] = 0u;

    // ---- parallel best-prior partial reduce (warp w = gt w) ----
    {
        unsigned long long key = 0xFFFFFFFFull;
        for (int blk = lane; blk < NBM; blk += 32) {
            unsigned long long x = g_bpp[((size_t)b * NBM + blk) * GG + w];
            if (x > key) key = x;
        }
#pragma unroll
        for (int o = 16; o; o >>= 1) {
            unsigned long long x = __shfl_xor_sync(0xffffffffu, key, o);
            if (x > key) key = x;
        }
        if (lane == 0) skey[w] = key;
    }
    __syncthreads();

    // ---- warp 0: duplicate resolution, claimed table + bitmap (smem only) ----
    if (t < GG) {
        unsigned aidx = 0xFFFFFFFFu - (unsigned)(skey[t] & 0xFFFFFFFFull);
        claimed_aidx[t] = aidx;
        __syncwarp();
        bool win = true;
        for (int g2 = t + 1; g2 < GG; g2++)
            if (claimed_aidx[g2] == aidx) win = false;  // later gt wins duplicates
        __syncwarp();
        if (win) {
            float4 gt = gt_boxes[b * GG + t];
            float4 an = anchors[aidx];
            float4 enc;
            enc.x = (gt.x - an.x) / an.z;
            enc.y = (gt.y - an.y) / an.w;
            enc.z = logf(gt.z) - logf(an.z);
            enc.w = logf(gt.w) - logf(an.w);
            claimed_enc[t] = enc;
            claimed_lab[t] = gt_labels[b * GG + t];
            atomicOr(&sbm[aidx >> 5], 1u << (aidx & 31));
        } else {
            claimed_aidx[t] = 0xFFFFFFFFu;
        }
    }
    __syncthreads();

    // ---- per-row: apply overrides, count positives, build mining values ----
    unsigned v[KV];
    float cp = 0.0f, ls = 0.0f;
    int np = 0;
#pragma unroll
    for (int it = 0; it < KV; it++) {
        int i = t + it * 1024;
        if (i < AA) {
            bool claimed = (sbm[i >> 5] >> (i & 31)) & 1u;
            int l = lab[it];
            float4 tl;
            bool have_tl = false;
            if (claimed) {
                for (int g = 0; g < GG; g++) {
                    if (claimed_aidx[g] == (unsigned)i) {
                        l = claimed_lab[g];
                        tl = claimed_enc[g];
                        have_tl = true;
                        break;
                    }
                }
            }
            bool pos = l > 0;
            if (pos) {
                np++;
                size_t row = (size_t)b * AA + i;
                if (!have_tl) tl = g_tloc[row];
                float c0   = conf[row * CC];
                float clab = conf[row * CC + l];
                cp += rawv[it] + c0 - clab;   // = lse - conf[lab]
                float4 lp = locp[row];
                ls += smooth_l1(lp.x - tl.x) + smooth_l1(lp.y - tl.y) +
                      smooth_l1(lp.z - tl.z) + smooth_l1(lp.w - tl.w);
                v[it] = 0u;
            } else {
                v[it] = __float_as_uint(rawv[it]);
            }
        } else v[it] = 0u;
    }
    {
        int x = np;
#pragma unroll
        for (int o = 16; o; o >>= 1) x += __shfl_xor_sync(0xffffffffu, x, o);
        if (lane == 0) siA[w] = x;
    }
    __syncthreads();
    if (t < 32) {
        int x = siA[t];
#pragma unroll
        for (int o = 16; o; o >>= 1) x += __shfl_xor_sync(0xffffffffu, x, o);
        if (t == 0) siA[32] = x;
    }
    __syncthreads();
    int np_total = siA[32];
    int k = min(NEG_RATIO * np_total, AA - 1);

    // ---- 3-round radix select ----
    float s = 0.0f;
    int cgt = 0;
    float vk = 0.0f;
    if (k > 0) {
#pragma unroll
        for (int it = 0; it < KV; it++) {
            int bin = (int)(v[it] >> 23);
            unsigned m = __match_any_sync(0xffffffffu, bin);
            if (lane == __ffs(m) - 1) atomicAdd(&h1[bin], __popc(m));
        }
        __syncthreads();
        find_bin_block(h1, 256, 1, k, sres, swarp);
        int E = sres[0];
        int k2 = k - sres[1];

#pragma unroll
        for (int it = 0; it < KV; it++) {
            if ((int)(v[it] >> 23) == E)
                atomicAdd(&h2[(v[it] >> 12) & 2047u], 1);
        }
        __syncthreads();
        find_bin_block(h2, 2048, 2, k2, sres, swarp);
        unsigned P = ((unsigned)E << 11) | (unsigned)sres[0];
        int k3 = k2 - sres[1];

#pragma unroll
        for (int it = 0; it < KV; it++) {
            if ((v[it] >> 12) == P)
                atomicAdd(&h3[v[it] & 4095u], 1);
        }
        __syncthreads();
        find_bin_block(h3, 4096, 4, k3, sres, swarp);
        unsigned lo = (P << 12) | (unsigned)sres[0];  // exact k-th largest bits
        vk = __uint_as_float(lo);

#pragma unroll
        for (int it = 0; it < KV; it++) {
            if (v[it] > lo) { s += __uint_as_float(v[it]); cgt++; }
        }
    }

    // ---- combined block reduce ----
#pragma unroll
    for (int o = 16; o; o >>= 1) {
        cp  += __shfl_xor_sync(0xffffffffu, cp, o);
        ls  += __shfl_xor_sync(0xffffffffu, ls, o);
        s   += __shfl_xor_sync(0xffffffffu, s, o);
        cgt += __shfl_xor_sync(0xffffffffu, cgt, o);
    }
    if (lane == 0) { sfA[w] = cp; sfB[w] = ls; sfC[w] = s; siB[w] = cgt; }
    __syncthreads();
    if (t == 0) {
        float cpt = 0.f, lst = 0.f, st = 0.f;
        int cgtt = 0;
#pragma unroll
        for (int w2 = 0; w2 < 32; w2++) {
            cpt += sfA[w2]; lst += sfB[w2]; st += sfC[w2]; cgtt += siB[w2];
        }
        float result = (k > 0) ? (st + (float)(k - cgtt) * vk) : 0.0f;
        g_bres[b] = make_float4(lst, cpt, result, (float)np_total);
        __threadfence();
        int done = atomicAdd(&g_done, 1);
        slast = (done == BB - 1) ? 1 : 0;
    }
    __syncthreads();

    // ---- last block: parallel final combine ----
    if (slast && w < 2) {  // threads 0..63, one per batch
        float4 r = g_bres[t];
        float loc = r.x, cpos = r.y, cn = r.z;
        int npb = (int)r.w;
        int nsb = npb + min(NEG_RATIO * npb, AA - 1);
#pragma unroll
        for (int o = 16; o; o >>= 1) {
            loc  += __shfl_xor_sync(0xffffffffu, loc, o);
            cpos += __shfl_xor_sync(0xffffffffu, cpos, o);
            cn   += __shfl_xor_sync(0xffffffffu, cn, o);
            npb  += __shfl_xor_sync(0xffffffffu, npb, o);
            nsb  += __shfl_xor_sync(0xffffffffu, nsb, o);
        }
        if (lane == 0) {
            sfA[w] = loc; sfB[w] = cpos; sfC[w] = cn;
            siA[w] = npb; siB[w] = nsb;
        }
        __syncwarp();
        if (t == 0) {
            float loct = sfA[0] + sfA[1];
            float cpt  = sfB[0] + sfB[1];
            float cnt  = sfC[0] + sfC[1];
            long long npt = siA[0] + siA[1];
            long long nst = siB[0] + siB[1];
            float cls = cpt + cnt +
                        (float)((long long)BB * AA - nst) * logf((float)CC);
            out[0] = (loct + cls) / (float)npt;
        }
    }
}

// ---------------- launch ----------------
extern "C" void kernel_launch(void* const* d_in, const int* in_sizes, int n_in,
                              void* d_out, int out_size) {
    const float4* loc_pred  = (const float4*)d_in[0];
    const float*  conf_pred = (const float*)d_in[1];
    const float4* anchors   = (const float4*)d_in[2];
    const float4* gt_boxes  = (const float4*)d_in[3];
    const int*    gt_labels = (const int*)d_in[4];
    float* out = (float*)d_out;

    dim3 gf(NBS + NBM, BB);   // 172 x 64 blocks of 256 threads
    f1_fused<<<gf, 256>>>(conf_pred, anchors, gt_boxes, gt_labels);

    k4_final<<<BB, 1024>>>(conf_pred, loc_pred, anchors, gt_boxes, gt_labels, out);
}

// round 17
// speedup vs baseline: 1.1207x; 1.0248x over previous
#include <cuda_runtime.h>
#include <math.h>

#define BB 64
#define AA 8732
#define CC 81
#define GG 32
#define NEG_RATIO 3
#define IOU_THR 0.5f
#define TROWS 128
#define NBS 69          // streaming blocks per batch: ceil(8732/128)
#define NBM 35          // matching blocks per batch: ceil(8732/256)

// ---------------- device scratch (no allocs allowed) ----------------
__device__ unsigned long long g_bpp[BB * NBM * GG]; // per-block best-prior partials
__device__ float              g_raw[BB * AA];       // lse - conf0 per row
__device__ int                g_pidx[BB * AA];      // compact positive list: anchor
__device__ int                g_plab[BB * AA];      //   label
__device__ float4             g_penc[BB * AA];      //   encoded loc target
__device__ int                g_nc[BB];             // list counts (k4 resets)
__device__ float4             g_bres[BB];
__device__ int                g_done;

__device__ __forceinline__ float smooth_l1(float d) {
    float ad = fabsf(d);
    return ad < 1.0f ? 0.5f * d * d : ad - 0.5f;
}

struct K1Smem {
    float gx1[GG], gy1[GG], gx2[GG], gy2[GG], garea[GG];
    float gcx[GG], gcy[GG], gw[GG], gh[GG];
    int   glab[GG];
    unsigned long long sbp[GG];
};

// ---------------- F1: fused conf-streaming (x<NBS) + matching (x>=NBS) ----------
__global__ void __launch_bounds__(256)
f1_fused(const float* __restrict__ conf,
         const float4* __restrict__ anchors,
         const float4* __restrict__ gt_boxes,
         const int*    __restrict__ gt_labels) {
    // 8 warps x 2 buffers x 324 floats = 20736 B
    __shared__ __align__(16) float sx[8 * 2 * 324];
    int b = blockIdx.y;
    int t = threadIdx.x;
    int w = t >> 5;
    int lane = t & 31;

    if (blockIdx.x >= NBS) {
        // ================= matching part (256 anchors/block) =================
        int bx = blockIdx.x - NBS;
        K1Smem* sm = reinterpret_cast<K1Smem*>(&sx[0]);

        if (bx == 0 && b == 0 && t == 0) g_done = 0;

        if (t < GG) {
            float4 g = gt_boxes[b * GG + t];
            float x1 = g.x - g.z * 0.5f, y1 = g.y - g.w * 0.5f;
            float x2 = g.x + g.z * 0.5f, y2 = g.y + g.w * 0.5f;
            sm->gx1[t] = x1; sm->gy1[t] = y1; sm->gx2[t] = x2; sm->gy2[t] = y2;
            sm->garea[t] = (x2 - x1) * (y2 - y1);
            sm->gcx[t] = g.x; sm->gcy[t] = g.y; sm->gw[t] = g.z; sm->gh[t] = g.w;
            sm->glab[t] = gt_labels[b * GG + t];
            sm->sbp[t] = 0xFFFFFFFFull;
        }
        __syncthreads();

        int a = bx * 256 + t;
        bool valid = a < AA;

        float4 an = valid ? anchors[a] : make_float4(2.0f, 2.0f, 0.01f, 0.01f);
        float ax1 = an.x - an.z * 0.5f, ay1 = an.y - an.w * 0.5f;
        float ax2 = an.x + an.z * 0.5f, ay2 = an.y + an.w * 0.5f;
        float aarea = (ax2 - ax1) * (ay2 - ay1);

        int warpbase = bx * 256 + (t & ~31);
        float best = -1.0f;
        int   bidx = 0;
#pragma unroll 4
        for (int g = 0; g < GG; g++) {
            float ltx = fmaxf(sm->gx1[g], ax1), lty = fmaxf(sm->gy1[g], ay1);
            float rbx = fminf(sm->gx2[g], ax2), rby = fminf(sm->gy2[g], ay2);
            float ww = fmaxf(rbx - ltx, 0.0f), hh = fmaxf(rby - lty, 0.0f);
            float inter = ww * hh;
            bool ov = valid && (inter > 0.0f);
            float iou = ov ? __fdividef(inter, sm->garea[g] + aarea - inter) : 0.0f;
            if (valid && iou > best) { best = iou; bidx = g; }

            if (__any_sync(0xffffffffu, ov)) {
                unsigned ib = ov ? __float_as_uint(iou) : 0u;
                unsigned mx = __reduce_max_sync(0xffffffffu, ib);
                unsigned ball = __ballot_sync(0xffffffffu, ib == mx);
                if (lane == 0) {
                    unsigned win_a = (unsigned)warpbase + (unsigned)(__ffs(ball) - 1);
                    unsigned long long key =
                        (((unsigned long long)mx) << 32) |
                        (unsigned long long)(0xFFFFFFFFu - win_a);
                    atomicMax(&sm->sbp[g], key);
                }
            }
        }

        // warp-aggregated append of threshold positives to compact list
        bool pos = valid && (best > IOU_THR);
        unsigned pm = __ballot_sync(0xffffffffu, pos);
        if (pm) {
            int leader = __ffs(pm) - 1;
            int basej = 0;
            if (lane == leader) basej = atomicAdd(&g_nc[b], __popc(pm));
            basej = __shfl_sync(0xffffffffu, basej, leader);
            if (pos) {
                int slot = basej + __popc(pm & ((1u << lane) - 1u));
                size_t e = (size_t)b * AA + slot;
                float4 enc;
                enc.x = (sm->gcx[bidx] - an.x) / an.z;
                enc.y = (sm->gcy[bidx] - an.y) / an.w;
                enc.z = logf(sm->gw[bidx]) - logf(an.z);
                enc.w = logf(sm->gh[bidx]) - logf(an.w);
                g_pidx[e] = a;
                g_plab[e] = sm->glab[bidx];
                g_penc[e] = enc;
            }
        }

        __syncthreads();
        if (t < GG)
            g_bpp[((size_t)b * NBM + bx) * GG + t] = sm->sbp[t];
        return;
    }

    // ===== conf streaming (R11-proven): warp-autonomous reg-pipelined groups =====
    int rowstart = blockIdx.x * TROWS;
    int nrows = min(TROWS, AA - rowstart);   // 128, tail 28 (%4==0)
    size_t growb = (size_t)b * AA + rowstart;
    const float4* gsrc = reinterpret_cast<const float4*>(conf + growb * CC);

    int base = w * 16;
    int ng = (base < nrows) ? min(4, (nrows - base) >> 2) : 0;
    const float4* wsrc = gsrc + w * 324;
    float* ws = sx + w * 648;

    float4 ra, rb4, rc;
    auto ldg = [&](int g) {
        const float4* p = wsrc + g * 81;
        ra  = __ldcs(p + lane);
        rb4 = __ldcs(p + lane + 32);
        if (lane < 17) rc = __ldcs(p + lane + 64);
    };
    auto sts = [&](int g) {
        float4* d = reinterpret_cast<float4*>(ws + (g & 1) * 324);
        d[lane] = ra;
        d[lane + 32] = rb4;
        if (lane < 17) d[lane + 64] = rc;
    };

    if (ng > 0) { ldg(0); sts(0); }
    __syncwarp();

    for (int g = 0; g < ng; g++) {
        if (g + 1 < ng) ldg(g + 1);

        const float* buf = ws + (g & 1) * 324;
        float e[4];
#pragma unroll
        for (int r = 0; r < 4; r++) {
            const float* row = buf + r * CC;
            float tv = __expf(row[lane]) + __expf(row[32 + lane]);
            if (lane < 17) tv += __expf(row[64 + lane]);
            e[r] = tv;
        }
#pragma unroll
        for (int o = 16; o; o >>= 1) {
#pragma unroll
            for (int r = 0; r < 4; r++)
                e[r] += __shfl_xor_sync(0xffffffffu, e[r], o);
        }
        if (lane == 0) {
            size_t rowb = growb + base + g * 4;
            float4 res;
            res.x = __logf(e[0]) - buf[0 * CC];
            res.y = __logf(e[1]) - buf[1 * CC];
            res.z = __logf(e[2]) - buf[2 * CC];
            res.w = __logf(e[3]) - buf[3 * CC];
            *reinterpret_cast<float4*>(g_raw + rowb) = res;  // raw = lse - conf0
        }
        __syncwarp();
        if (g + 1 < ng) { sts(g + 1); __syncwarp(); }
    }
}

// ---------------- block-parallel descending bin search ----------------
__device__ __forceinline__ void find_bin_block(const int* h, int N, int P, int k,
                                               int* sres, int* swarp) {
    int t = threadIdx.x, lane = t & 31, w = t >> 5;
    int nt = N / P;
    int local = 0;
    if (t < nt)
        for (int j = 0; j < P; j++) local += h[t * P + j];
    int suf = local;
#pragma unroll
    for (int o = 1; o < 32; o <<= 1) {
        int x = __shfl_down_sync(0xffffffffu, suf, o);
        if (lane + o < 32) suf += x;
    }
    if (t < nt && lane == 0) swarp[w] = suf;
    __syncthreads();
    if (t < nt) {
        int nw = nt >> 5;
        int above = suf - local;
        for (int w2 = w + 1; w2 < nw; w2++) above += swarp[w2];
        if (above < k && k <= above + local) {
            int acc = above, bin = t * P;
            for (int j = P - 1; j >= 0; j--) {
                int c = h[t * P + j];
                if (k <= acc + c) { bin = t * P + j; break; }
                acc += c;
            }
            sres[0] = bin; sres[1] = acc;
        }
    }
    __syncthreads();
}

// ---------------- K4': list-based positives + radix top-k + final --------
#define KV 9      // ceil(AA/1024)
#define NBMW 273  // ceil(AA/32) bitmap words

__global__ void __launch_bounds__(1024)
k4_final(const float* __restrict__ conf,
         const float4* __restrict__ locp,
         const float4* __restrict__ anchors,
         const float4* __restrict__ gt_boxes,
         const int*    __restrict__ gt_labels,
         float* __restrict__ out) {
    __shared__ int h1[256];
    __shared__ int h2[2048];
    __shared__ int h3[4096];
    __shared__ unsigned sbm[NBMW];
    __shared__ unsigned claimed_aidx[GG];
    __shared__ int      claimed_lab[GG];
    __shared__ float4   claimed_enc[GG];
    __shared__ unsigned long long skey[GG];
    __shared__ int swarp[32];
    __shared__ int sres[2];
    __shared__ float sfA[32], sfB[32], sfC[32];
    __shared__ int siA[33], siB[32];
    __shared__ int slast;
    int b = blockIdx.x;
    int t = threadIdx.x;
    int lane = t & 31, w = t >> 5;

    // ---- prefetch raw (only dense array k4 needs) ----
    float rawv[KV];
#pragma unroll
    for (int it = 0; it < KV; it++) {
        int i = t + it * 1024;
        rawv[it] = (i < AA) ? g_raw[(size_t)b * AA + i] : 0.0f;
    }
    int nc = g_nc[b];
    for (int i = t; i < 256;  i += 1024) h1[i] = 0;
    for (int i = t; i < 2048; i += 1024) h2[i] = 0;
    for (int i = t; i < 4096; i += 1024) h3[i] = 0;
    for (int i = t; i < NBMW; i += 1024) sbm[i] = 0u;

    // ---- parallel best-prior partial reduce (warp w = gt w) ----
    {
        unsigned long long key = 0xFFFFFFFFull;
        for (int blk = lane; blk < NBM; blk += 32) {
            unsigned long long x = g_bpp[((size_t)b * NBM + blk) * GG + w];
            if (x > key) key = x;
        }
#pragma unroll
        for (int o = 16; o; o >>= 1) {
            unsigned long long x = __shfl_xor_sync(0xffffffffu, key, o);
            if (x > key) key = x;
        }
        if (lane == 0) skey[w] = key;
    }
    __syncthreads();

    // ---- warp 0: duplicate resolution + claimed table; others mark list bitmap ----
    if (t < GG) {
        unsigned aidx = 0xFFFFFFFFu - (unsigned)(skey[t] & 0xFFFFFFFFull);
        claimed_aidx[t] = aidx;
        __syncwarp();
        bool win = true;
        for (int g2 = t + 1; g2 < GG; g2++)
            if (claimed_aidx[g2] == aidx) win = false;  // later gt wins duplicates
        __syncwarp();
        if (win) {
            float4 gt = gt_boxes[b * GG + t];
            float4 an = anchors[aidx];
            float4 enc;
            enc.x = (gt.x - an.x) / an.z;
            enc.y = (gt.y - an.y) / an.w;
            enc.z = logf(gt.z) - logf(an.z);
            enc.w = logf(gt.w) - logf(an.w);
            claimed_enc[t] = enc;
            claimed_lab[t] = gt_labels[b * GG + t];
            atomicOr(&sbm[aidx >> 5], 1u << (aidx & 31));
        } else {
            claimed_aidx[t] = 0xFFFFFFFFu;
        }
    }
    // mark threshold positives in bitmap (all threads, list is short)
    for (int j = t; j < nc; j += 1024) {
        int a = g_pidx[(size_t)b * AA + j];
        atomicOr(&sbm[a >> 5], 1u << (a & 31));
    }
    __syncthreads();

    // ---- np = popcount of union bitmap ----
    int np = 0;
    for (int i = t; i < NBMW; i += 1024) np += __popc(sbm[i]);
#pragma unroll
    for (int o = 16; o; o >>= 1) np += __shfl_xor_sync(0xffffffffu, np, o);
    if (lane == 0) siA[w] = np;
    __syncthreads();
    if (t < 32) {
        int x = siA[t];
#pragma unroll
        for (int o = 16; o; o >>= 1) x += __shfl_xor_sync(0xffffffffu, x, o);
        if (t == 0) siA[32] = x;
    }
    __syncthreads();
    int np_total = siA[32];
    int k = min(NEG_RATIO * np_total, AA - 1);

    // ---- positive losses: list entries (skip claimed) + claimed table ----
    float cp = 0.0f, ls = 0.0f;
    for (int j = t; j < nc; j += 1024) {
        size_t e = (size_t)b * AA + j;
        unsigned a = (unsigned)g_pidx[e];
        bool skip = false;
#pragma unroll
        for (int g = 0; g < GG; g++)
            if (claimed_aidx[g] == a) skip = true;   // claimed overrides
        if (!skip) {
            int l = g_plab[e];
            float4 tl = g_penc[e];
            size_t row = (size_t)b * AA + a;
            float raw = g_raw[row];
            float c0   = conf[row * CC];
            float clab = conf[row * CC + l];
            cp += raw + c0 - clab;                    // = lse - conf[lab]
            float4 lp = locp[row];
            ls += smooth_l1(lp.x - tl.x) + smooth_l1(lp.y - tl.y) +
                  smooth_l1(lp.z - tl.z) + smooth_l1(lp.w - tl.w);
        }
    }
    if (t < GG && claimed_aidx[t] != 0xFFFFFFFFu) {
        unsigned a = claimed_aidx[t];
        int l = claimed_lab[t];
        float4 tl = claimed_enc[t];
        size_t row = (size_t)b * AA + a;
        float raw = g_raw[row];
        float c0   = conf[row * CC];
        float clab = conf[row * CC + l];
        cp += raw + c0 - clab;
        float4 lp = locp[row];
        ls += smooth_l1(lp.x - tl.x) + smooth_l1(lp.y - tl.y) +
              smooth_l1(lp.z - tl.z) + smooth_l1(lp.w - tl.w);
    }

    // ---- mining values: raw unless positive (bitmap) ----
    unsigned v[KV];
#pragma unroll
    for (int it = 0; it < KV; it++) {
        int i = t + it * 1024;
        bool neg = (i < AA) && !((sbm[i >> 5] >> (i & 31)) & 1u);
        v[it] = neg ? __float_as_uint(rawv[it]) : 0u;
    }

    // ---- 3-round radix select ----
    float s = 0.0f;
    int cgt = 0;
    float vk = 0.0f;
    if (k > 0) {
#pragma unroll
        for (int it = 0; it < KV; it++) {
            int bin = (int)(v[it] >> 23);
            unsigned m = __match_any_sync(0xffffffffu, bin);
            if (lane == __ffs(m) - 1) atomicAdd(&h1[bin], __popc(m));
        }
        __syncthreads();
        find_bin_block(h1, 256, 1, k, sres, swarp);
        int E = sres[0];
        int k2 = k - sres[1];

#pragma unroll
        for (int it = 0; it < KV; it++) {
            if ((int)(v[it] >> 23) == E)
                atomicAdd(&h2[(v[it] >> 12) & 2047u], 1);
        }
        __syncthreads();
        find_bin_block(h2, 2048, 2, k2, sres, swarp);
        unsigned P = ((unsigned)E << 11) | (unsigned)sres[0];
        int k3 = k2 - sres[1];

#pragma unroll
        for (int it = 0; it < KV; it++) {
            if ((v[it] >> 12) == P)
                atomicAdd(&h3[v[it] & 4095u], 1);
        }
        __syncthreads();
        find_bin_block(h3, 4096, 4, k3, sres, swarp);
        unsigned lo = (P << 12) | (unsigned)sres[0];  // exact k-th largest bits
        vk = __uint_as_float(lo);

#pragma unroll
        for (int it = 0; it < KV; it++) {
            if (v[it] > lo) { s += __uint_as_float(v[it]); cgt++; }
        }
    }

    // ---- combined block reduce ----
#pragma unroll
    for (int o = 16; o; o >>= 1) {
        cp  += __shfl_xor_sync(0xffffffffu, cp, o);
        ls  += __shfl_xor_sync(0xffffffffu, ls, o);
        s   += __shfl_xor_sync(0xffffffffu, s, o);
        cgt += __shfl_xor_sync(0xffffffffu, cgt, o);
    }
    if (lane == 0) { sfA[w] = cp; sfB[w] = ls; sfC[w] = s; siB[w] = cgt; }
    __syncthreads();
    if (t == 0) {
        float cpt = 0.f, lst = 0.f, st = 0.f;
        int cgtt = 0;
#pragma unroll
        for (int w2 = 0; w2 < 32; w2++) {
            cpt += sfA[w2]; lst += sfB[w2]; st += sfC[w2]; cgtt += siB[w2];
        }
        float result = (k > 0) ? (st + (float)(k - cgtt) * vk) : 0.0f;
        g_bres[b] = make_float4(lst, cpt, result, (float)np_total);
        g_nc[b] = 0;   // reset list counter for next replay
        __threadfence();
        int done = atomicAdd(&g_done, 1);
        slast = (done == BB - 1) ? 1 : 0;
    }
    __syncthreads();

    // ---- last block: parallel final combine ----
    if (slast && w < 2) {  // threads 0..63, one per batch
        float4 r = g_bres[t];
        float loc = r.x, cpos = r.y, cn = r.z;
        int npb = (int)r.w;
        int nsb = npb + min(NEG_RATIO * npb, AA - 1);
#pragma unroll
        for (int o = 16; o; o >>= 1) {
            loc  += __shfl_xor_sync(0xffffffffu, loc, o);
            cpos += __shfl_xor_sync(0xffffffffu, cpos, o);
            cn   += __shfl_xor_sync(0xffffffffu, cn, o);
            npb  += __shfl_xor_sync(0xffffffffu, npb, o);
            nsb  += __shfl_xor_sync(0xffffffffu, nsb, o);
        }
        if (lane == 0) {
            sfA[w] = loc; sfB[w] = cpos; sfC[w] = cn;
            siA[w] = npb; siB[w] = nsb;
        }
        __syncwarp();
        if (t == 0) {
            float loct = sfA[0] + sfA[1];
            float cpt  = sfB[0] + sfB[1];
            float cnt  = sfC[0] + sfC[1];
            long long npt = siA[0] + siA[1];
            long long nst = siB[0] + siB[1];
            float cls = cpt + cnt +
                        (float)((long long)BB * AA - nst) * logf((float)CC);
            out[0] = (loct + cls) / (float)npt;
        }
    }
}

// ---------------- launch ----------------
extern "C" void kernel_launch(void* const* d_in, const int* in_sizes, int n_in,
                              void* d_out, int out_size) {
    const float4* loc_pred  = (const float4*)d_in[0];
    const float*  conf_pred = (const float*)d_in[1];
    const float4* anchors   = (const float4*)d_in[2];
    const float4* gt_boxes  = (const float4*)d_in[3];
    const int*    gt_labels = (const int*)d_in[4];
    float* out = (float*)d_out;

    dim3 gf(NBS + NBM, BB);   // 104 x 64 blocks of 256 threads
    f1_fused<<<gf, 256>>>(conf_pred, anchors, gt_boxes, gt_labels);

    k4_final<<<BB, 1024>>>(conf_pred, loc_pred, anchors, gt_boxes, gt_labels, out);
}